// round 2
// baseline (speedup 1.0000x reference)
#include <cuda_runtime.h>
#include <math.h>
#include <stdint.h>

#define T_TOK 8192
#define H_DIM 1024
#define F_DIM 4096
#define NE    8

// Scratch (static device globals — no allocation in kernel_launch)
__device__ float g_h[(size_t)T_TOK * F_DIM];   // per-expert hidden, reused across experts
__device__ int   g_tok[NE * T_TOK];            // compacted token lists
__device__ float g_wt[NE * T_TOK];             // per-(expert,pos) routing weight
__device__ int   g_cnt[NE];                    // per-expert counts

__global__ void zero_counts_kernel() {
    if (threadIdx.x < NE) g_cnt[threadIdx.x] = 0;
}

// One warp per token: logits = x @ router_w + router_b; top-2; softmax over the two.
__global__ __launch_bounds__(256) void router_kernel(const float* __restrict__ x,
                                                     const float* __restrict__ rw,
                                                     const float* __restrict__ rb) {
    int warp = threadIdx.x >> 5;
    int lane = threadIdx.x & 31;
    int t = blockIdx.x * 8 + warp;
    if (t >= T_TOK) return;
    const float* xr = x + (size_t)t * H_DIM;
    float acc[NE];
#pragma unroll
    for (int e = 0; e < NE; e++) acc[e] = 0.f;
    for (int h = lane; h < H_DIM; h += 32) {
        float xv = xr[h];
        const float* wr = rw + h * NE;
#pragma unroll
        for (int e = 0; e < NE; e++) acc[e] += xv * wr[e];
    }
#pragma unroll
    for (int off = 16; off > 0; off >>= 1) {
#pragma unroll
        for (int e = 0; e < NE; e++)
            acc[e] += __shfl_xor_sync(0xffffffffu, acc[e], off);
    }
    if (lane == 0) {
#pragma unroll
        for (int e = 0; e < NE; e++) acc[e] += rb[e];
        int i1 = 0;
#pragma unroll
        for (int e = 1; e < NE; e++) if (acc[e] > acc[i1]) i1 = e;
        int i2 = -1;
#pragma unroll
        for (int e = 0; e < NE; e++) {
            if (e == i1) continue;
            if (i2 < 0 || acc[e] > acc[i2]) i2 = e;
        }
        // renormalized top-2 softmax == softmax over {l1, l2}
        float d   = acc[i2] - acc[i1];          // <= 0
        float w1p = 1.f / (1.f + expf(d));
        float w2p = 1.f - w1p;
        int p1 = atomicAdd(&g_cnt[i1], 1);
        g_tok[i1 * T_TOK + p1] = t;
        g_wt [i1 * T_TOK + p1] = w1p;
        int p2 = atomicAdd(&g_cnt[i2], 1);
        g_tok[i2 * T_TOK + p2] = t;
        g_wt [i2 * T_TOK + p2] = w2p;
    }
}

__device__ __forceinline__ float gelu_tanh(float v) {
    // jax.nn.gelu default: approximate=True (tanh form)
    float u = 0.7978845608028654f * (v + 0.044715f * v * v * v);
    return 0.5f * v * (1.0f + tanhf(u));
}

#define BM 128
#define BN 128
#define BK 8

// GEMM1: h[pos, f] = gelu( x[tok[pos], :] @ w1[e] + b1[e] ),  pos < cnt[e]
// 256 threads, 8x8 per thread, register-prefetch double buffering.
__global__ __launch_bounds__(256, 2) void gemm1_kernel(const float* __restrict__ x,
                                                       const float* __restrict__ w1,
                                                       const float* __restrict__ b1,
                                                       int e) {
    int cnt = g_cnt[e];
    int row0 = blockIdx.y * BM;
    if (row0 >= cnt) return;
    int col0 = blockIdx.x * BN;

    __shared__ float As[BK][BM];
    __shared__ float Bs[BK][BN];
    __shared__ int   toks[BM];

    int tid = threadIdx.x;
    if (tid < BM) {
        int p = row0 + tid;
        toks[tid] = (p < cnt) ? g_tok[e * T_TOK + p] : -1;
    }
    __syncthreads();

    const float* Bp = w1 + (size_t)e * H_DIM * F_DIM;
    int am = tid >> 1;            // 0..127
    int ak = (tid & 1) * 4;       // 0 or 4
    int br = tid >> 5;            // 0..7
    int bc = (tid & 31) * 4;      // 0..124
    int ty = tid >> 4, tx = tid & 15;

    int tokA = toks[am];
    const float* xrow = (tokA >= 0) ? (x + (size_t)tokA * H_DIM) : x;

    float acc[8][8];
#pragma unroll
    for (int i = 0; i < 8; i++)
#pragma unroll
        for (int j = 0; j < 8; j++) acc[i][j] = 0.f;

    // prefetch first tile
    float4 a_nx = make_float4(0.f, 0.f, 0.f, 0.f);
    if (tokA >= 0) a_nx = *(const float4*)(xrow + ak);
    float4 b_nx = *(const float4*)(Bp + (size_t)br * F_DIM + col0 + bc);

    for (int k0 = 0; k0 < H_DIM; k0 += BK) {
        As[ak + 0][am] = a_nx.x;
        As[ak + 1][am] = a_nx.y;
        As[ak + 2][am] = a_nx.z;
        As[ak + 3][am] = a_nx.w;
        *(float4*)&Bs[br][bc] = b_nx;
        __syncthreads();

        int kn = k0 + BK;
        if (kn < H_DIM) {
            if (tokA >= 0) a_nx = *(const float4*)(xrow + kn + ak);
            b_nx = *(const float4*)(Bp + (size_t)(kn + br) * F_DIM + col0 + bc);
        }

#pragma unroll
        for (int k = 0; k < BK; k++) {
            float4 a0 = *(float4*)&As[k][ty * 8];
            float4 a1 = *(float4*)&As[k][ty * 8 + 4];
            float4 b0 = *(float4*)&Bs[k][tx * 8];
            float4 b1 = *(float4*)&Bs[k][tx * 8 + 4];
            float a[8] = {a0.x, a0.y, a0.z, a0.w, a1.x, a1.y, a1.z, a1.w};
            float b[8] = {b0.x, b0.y, b0.z, b0.w, b1.x, b1.y, b1.z, b1.w};
#pragma unroll
            for (int i = 0; i < 8; i++)
#pragma unroll
                for (int j = 0; j < 8; j++) acc[i][j] += a[i] * b[j];
        }
        __syncthreads();
    }

    const float* bb = b1 + e * F_DIM + col0 + tx * 8;
    float bv[8];
#pragma unroll
    for (int j = 0; j < 8; j++) bv[j] = bb[j];
#pragma unroll
    for (int i = 0; i < 8; i++) {
        int pos = row0 + ty * 8 + i;
        if (pos >= cnt) continue;
        float* hr = g_h + (size_t)pos * F_DIM + col0 + tx * 8;
        float4 o0, o1;
        o0.x = gelu_tanh(acc[i][0] + bv[0]);
        o0.y = gelu_tanh(acc[i][1] + bv[1]);
        o0.z = gelu_tanh(acc[i][2] + bv[2]);
        o0.w = gelu_tanh(acc[i][3] + bv[3]);
        o1.x = gelu_tanh(acc[i][4] + bv[4]);
        o1.y = gelu_tanh(acc[i][5] + bv[5]);
        o1.z = gelu_tanh(acc[i][6] + bv[6]);
        o1.w = gelu_tanh(acc[i][7] + bv[7]);
        *(float4*)(hr)     = o0;
        *(float4*)(hr + 4) = o1;
    }
}

// GEMM2: out[tok[pos], :] += wt[pos] * ( h[pos, :] @ w2[e] + b2[e] )
__global__ __launch_bounds__(256, 2) void gemm2_kernel(const float* __restrict__ w2,
                                                       const float* __restrict__ b2,
                                                       float* __restrict__ out,
                                                       int e) {
    int cnt = g_cnt[e];
    int row0 = blockIdx.y * BM;
    if (row0 >= cnt) return;
    int col0 = blockIdx.x * BN;

    __shared__ float As[BK][BM];
    __shared__ float Bs[BK][BN];
    __shared__ int   toks[BM];
    __shared__ float wts[BM];

    int tid = threadIdx.x;
    if (tid < BM) {
        int p = row0 + tid;
        toks[tid] = (p < cnt) ? g_tok[e * T_TOK + p] : -1;
        wts[tid]  = (p < cnt) ? g_wt[e * T_TOK + p] : 0.f;
    }
    __syncthreads();

    const float* Bp = w2 + (size_t)e * F_DIM * H_DIM;
    int am = tid >> 1;
    int ak = (tid & 1) * 4;
    int br = tid >> 5;
    int bc = (tid & 31) * 4;
    int ty = tid >> 4, tx = tid & 15;

    // rows >= cnt read stale g_h but are never written out (guard in epilogue)
    int arow_idx = (row0 + am < T_TOK) ? (row0 + am) : 0;
    const float* arow = g_h + (size_t)arow_idx * F_DIM;

    float acc[8][8];
#pragma unroll
    for (int i = 0; i < 8; i++)
#pragma unroll
        for (int j = 0; j < 8; j++) acc[i][j] = 0.f;

    float4 a_nx = *(const float4*)(arow + ak);
    float4 b_nx = *(const float4*)(Bp + (size_t)br * H_DIM + col0 + bc);

    for (int k0 = 0; k0 < F_DIM; k0 += BK) {
        As[ak + 0][am] = a_nx.x;
        As[ak + 1][am] = a_nx.y;
        As[ak + 2][am] = a_nx.z;
        As[ak + 3][am] = a_nx.w;
        *(float4*)&Bs[br][bc] = b_nx;
        __syncthreads();

        int kn = k0 + BK;
        if (kn < F_DIM) {
            a_nx = *(const float4*)(arow + kn + ak);
            b_nx = *(const float4*)(Bp + (size_t)(kn + br) * H_DIM + col0 + bc);
        }

#pragma unroll
        for (int k = 0; k < BK; k++) {
            float4 a0 = *(float4*)&As[k][ty * 8];
            float4 a1 = *(float4*)&As[k][ty * 8 + 4];
            float4 b0 = *(float4*)&Bs[k][tx * 8];
            float4 b1 = *(float4*)&Bs[k][tx * 8 + 4];
            float a[8] = {a0.x, a0.y, a0.z, a0.w, a1.x, a1.y, a1.z, a1.w};
            float b[8] = {b0.x, b0.y, b0.z, b0.w, b1.x, b1.y, b1.z, b1.w};
#pragma unroll
            for (int i = 0; i < 8; i++)
#pragma unroll
                for (int j = 0; j < 8; j++) acc[i][j] += a[i] * b[j];
        }
        __syncthreads();
    }

    const float* bb = b2 + e * H_DIM + col0 + tx * 8;
    float bv[8];
#pragma unroll
    for (int j = 0; j < 8; j++) bv[j] = bb[j];
#pragma unroll
    for (int i = 0; i < 8; i++) {
        int pos = row0 + ty * 8 + i;
        if (pos >= cnt) continue;
        int   t  = toks[ty * 8 + i];
        float wv = wts [ty * 8 + i];
        float* orow = out + (size_t)t * H_DIM + col0 + tx * 8;
#pragma unroll
        for (int j = 0; j < 8; j++) {
            atomicAdd(&orow[j], wv * (acc[i][j] + bv[j]));
        }
    }
}

extern "C" void kernel_launch(void* const* d_in, const int* in_sizes, int n_in,
                              void* d_out, int out_size) {
    const float* x  = (const float*)d_in[0];  // [B,S,H]
    const float* w1 = (const float*)d_in[1];  // [E,H,F]
    const float* b1 = (const float*)d_in[2];  // [E,F]
    const float* w2 = (const float*)d_in[3];  // [E,F,H]
    const float* b2 = (const float*)d_in[4];  // [E,H]
    const float* rw = (const float*)d_in[5];  // [H,E]
    const float* rb = (const float*)d_in[6];  // [E]
    float* out = (float*)d_out;

    cudaMemsetAsync(out, 0, (size_t)T_TOK * H_DIM * sizeof(float), 0);
    zero_counts_kernel<<<1, 32>>>();
    router_kernel<<<T_TOK / 8, 256>>>(x, rw, rb);

    dim3 block(256);
    dim3 grid1(F_DIM / BN, T_TOK / BM);   // 32 x 64
    dim3 grid2(H_DIM / BN, T_TOK / BM);   //  8 x 64
    for (int e = 0; e < NE; e++) {
        gemm1_kernel<<<grid1, block>>>(x, w1, b1, e);
        gemm2_kernel<<<grid2, block>>>(w2, b2, out, e);
    }
}

// round 5
// speedup vs baseline: 5.2452x; 5.2452x over previous
#include <cuda_runtime.h>
#include <math.h>
#include <stdint.h>

#define T_TOK 8192
#define H_DIM 1024
#define F_DIM 4096
#define NE    8
#define BM    128
#define BN    128
#define BK    32

// ---------------- device scratch (static, no runtime allocation) ------------
__device__ float g_h [(size_t)(2 * T_TOK + BM) * F_DIM];  // gelu(x@w1+b1) per slot
__device__ float g_h2[(size_t)(2 * T_TOK + BM) * H_DIM];  // (h@w2+b2) per slot
__device__ int   g_tok[NE * T_TOK];
__device__ int   g_cnt[NE];
__device__ int   g_off[NE];
__device__ int   g_pE[2 * T_TOK];    // per token: expert of routed slot j
__device__ int   g_pP[2 * T_TOK];    // per token: position within expert list
__device__ float g_pW[2 * T_TOK];    // per token: routing weight

// ---------------- small helpers ---------------------------------------------
__device__ __forceinline__ uint32_t f2tf(float f) {
    uint32_t u;
    asm("cvt.rna.tf32.f32 %0, %1;" : "=r"(u) : "f"(f));
    return u;
}
__device__ __forceinline__ void mma8(float* d, const uint32_t* a, const uint32_t* b) {
    asm volatile(
        "mma.sync.aligned.m16n8k8.row.col.f32.tf32.tf32.f32 "
        "{%0,%1,%2,%3}, {%4,%5,%6,%7}, {%8,%9}, {%0,%1,%2,%3};"
        : "+f"(d[0]), "+f"(d[1]), "+f"(d[2]), "+f"(d[3])
        : "r"(a[0]), "r"(a[1]), "r"(a[2]), "r"(a[3]), "r"(b[0]), "r"(b[1]));
}
__device__ __forceinline__ float gelu_tanh(float v) {
    float u = 0.7978845608028654f * (v + 0.044715f * v * v * v);
    return 0.5f * v * (1.0f + tanhf(u));
}

// ---------------- router ------------------------------------------------------
__global__ void zero_counts_kernel() {
    if (threadIdx.x < NE) g_cnt[threadIdx.x] = 0;
}
__global__ void scan_kernel() {
    if (threadIdx.x == 0) {
        int s = 0;
        for (int e = 0; e < NE; e++) { g_off[e] = s; s += g_cnt[e]; }
    }
}
__global__ __launch_bounds__(256) void router_kernel(const float* __restrict__ x,
                                                     const float* __restrict__ rw,
                                                     const float* __restrict__ rb) {
    int warp = threadIdx.x >> 5, lane = threadIdx.x & 31;
    int t = blockIdx.x * 8 + warp;
    if (t >= T_TOK) return;
    const float* xr = x + (size_t)t * H_DIM;
    float acc[NE];
#pragma unroll
    for (int e = 0; e < NE; e++) acc[e] = 0.f;
    for (int h = lane; h < H_DIM; h += 32) {
        float xv = xr[h];
        const float* wr = rw + h * NE;
#pragma unroll
        for (int e = 0; e < NE; e++) acc[e] += xv * wr[e];
    }
#pragma unroll
    for (int off = 16; off > 0; off >>= 1)
#pragma unroll
        for (int e = 0; e < NE; e++) acc[e] += __shfl_xor_sync(0xffffffffu, acc[e], off);
    if (lane == 0) {
#pragma unroll
        for (int e = 0; e < NE; e++) acc[e] += rb[e];
        int i1 = 0;
#pragma unroll
        for (int e = 1; e < NE; e++) if (acc[e] > acc[i1]) i1 = e;
        int i2 = -1;
#pragma unroll
        for (int e = 0; e < NE; e++) {
            if (e == i1) continue;
            if (i2 < 0 || acc[e] > acc[i2]) i2 = e;
        }
        float d   = acc[i2] - acc[i1];
        float w1p = 1.f / (1.f + expf(d));
        float w2p = 1.f - w1p;
        int p1 = atomicAdd(&g_cnt[i1], 1);
        g_tok[i1 * T_TOK + p1] = t;
        g_pE[2 * t] = i1; g_pP[2 * t] = p1; g_pW[2 * t] = w1p;
        int p2 = atomicAdd(&g_cnt[i2], 1);
        g_tok[i2 * T_TOK + p2] = t;
        g_pE[2 * t + 1] = i2; g_pP[2 * t + 1] = p2; g_pW[2 * t + 1] = w2p;
    }
}

// ---------------- tf32 mma.sync GEMM (both phases) ---------------------------
// smem layout (uint32 words): As[2][128*36] then Bs[2][32*136]
#define AS_STRIDE 36
#define BS_STRIDE 136
#define AS_WORDS  (BM * AS_STRIDE)      // 4608
#define BS_WORDS  (BK * BS_STRIDE)      // 4352
#define SMEM_WORDS (2 * AS_WORDS + 2 * BS_WORDS)
#define SMEM_DYN   (SMEM_WORDS * 4)     // 71680 bytes

template <bool PHASE2>
__global__ __launch_bounds__(256) void moe_mma(const float* __restrict__ X,
                                               const float* __restrict__ W,
                                               const float* __restrict__ Bias) {
    constexpr int KDIM   = PHASE2 ? F_DIM : H_DIM;
    constexpr int NDIM   = PHASE2 ? H_DIM : F_DIM;
    constexpr int STAGES = KDIM / BK;

    const int e    = blockIdx.z;
    const int cnt  = g_cnt[e];
    const int row0 = blockIdx.y * BM;
    if (row0 >= cnt) return;
    const int col0 = blockIdx.x * BN;
    const int off  = g_off[e];

    // ***** per-expert weight base (the round-4 bug: this offset was missing) *****
    const float* Wexp = W + (size_t)e * KDIM * NDIM;

    extern __shared__ uint32_t smu[];
    uint32_t* AS[2] = {smu, smu + AS_WORDS};
    uint32_t* BS[2] = {smu + 2 * AS_WORDS, smu + 2 * AS_WORDS + BS_WORDS};

    __shared__ int toks_s[BM];
    const int tid = threadIdx.x;
    if (!PHASE2 && tid < BM) {
        int pos = row0 + tid;
        toks_s[tid] = (pos < cnt) ? g_tok[e * T_TOK + pos] : -1;
    }
    __syncthreads();

    // A loader mapping: row = tid>>1 (0..127), khalf = tid&1 (16 floats each)
    const int arow = tid >> 1, kh = tid & 1;
    const float* aptr;
    if (PHASE2) {
        aptr = g_h + (size_t)(off + row0 + arow) * F_DIM;
    } else {
        int tk = toks_s[arow];
        aptr = (tk >= 0) ? (X + (size_t)tk * H_DIM) : nullptr;
    }
    // B loader mapping: k = (tid>>5) + i*8, 4 floats at n = (tid&31)*4
    const int bwarp = tid >> 5, blane = tid & 31;
    const float* bbase = Wexp + (size_t)bwarp * NDIM + col0 + blane * 4;

    const int lane = tid & 31;
    const int g  = lane >> 2, t4 = lane & 3;
    const int wm = (tid >> 5) >> 2, wn = (tid >> 5) & 3;

    float acc[4][4][4];
#pragma unroll
    for (int mt = 0; mt < 4; mt++)
#pragma unroll
        for (int nt = 0; nt < 4; nt++)
#pragma unroll
            for (int r = 0; r < 4; r++) acc[mt][nt][r] = 0.f;

    float4 av[4], bv[4];

    // ---- prologue: load + store stage 0
#pragma unroll
    for (int j = 0; j < 4; j++)
        av[j] = aptr ? *(const float4*)(aptr + kh * 16 + j * 4)
                     : make_float4(0.f, 0.f, 0.f, 0.f);
#pragma unroll
    for (int i = 0; i < 4; i++)
        bv[i] = *(const float4*)(bbase + (size_t)(i * 8) * NDIM);
    {
        uint32_t* A = AS[0];
        uint32_t* B = BS[0];
#pragma unroll
        for (int j = 0; j < 4; j++) {
            uint4 u = {f2tf(av[j].x), f2tf(av[j].y), f2tf(av[j].z), f2tf(av[j].w)};
            *(uint4*)(A + arow * AS_STRIDE + kh * 16 + j * 4) = u;
        }
#pragma unroll
        for (int i = 0; i < 4; i++) {
            uint4 u = {f2tf(bv[i].x), f2tf(bv[i].y), f2tf(bv[i].z), f2tf(bv[i].w)};
            *(uint4*)(B + (bwarp + i * 8) * BS_STRIDE + blane * 4) = u;
        }
    }
    __syncthreads();

    for (int s = 0; s < STAGES; s++) {
        const int buf = s & 1;
        // prefetch stage s+1 from gmem
        if (s + 1 < STAGES) {
            int k0 = (s + 1) * BK;
#pragma unroll
            for (int j = 0; j < 4; j++)
                av[j] = aptr ? *(const float4*)(aptr + k0 + kh * 16 + j * 4)
                             : make_float4(0.f, 0.f, 0.f, 0.f);
#pragma unroll
            for (int i = 0; i < 4; i++)
                bv[i] = *(const float4*)(bbase + (size_t)(k0 + i * 8) * NDIM);
        }
        // compute on buf
        {
            const uint32_t* A = AS[buf];
            const uint32_t* B = BS[buf];
#pragma unroll
            for (int ks = 0; ks < 4; ks++) {
                uint32_t af[4][4], bf[4][2];
#pragma unroll
                for (int mt = 0; mt < 4; mt++) {
                    const uint32_t* ap =
                        A + (wm * 64 + mt * 16 + g) * AS_STRIDE + ks * 8 + t4;
                    af[mt][0] = ap[0];
                    af[mt][1] = ap[8 * AS_STRIDE];
                    af[mt][2] = ap[4];
                    af[mt][3] = ap[8 * AS_STRIDE + 4];
                }
#pragma unroll
                for (int nt = 0; nt < 4; nt++) {
                    const uint32_t* bp =
                        B + (ks * 8 + t4) * BS_STRIDE + wn * 32 + nt * 8 + g;
                    bf[nt][0] = bp[0];
                    bf[nt][1] = bp[4 * BS_STRIDE];
                }
#pragma unroll
                for (int mt = 0; mt < 4; mt++)
#pragma unroll
                    for (int nt = 0; nt < 4; nt++) mma8(acc[mt][nt], af[mt], bf[nt]);
            }
        }
        // store stage s+1 into the other buffer (safe: all threads synced past
        // their reads of that buffer at the end of the previous iteration)
        if (s + 1 < STAGES) {
            uint32_t* A = AS[buf ^ 1];
            uint32_t* B = BS[buf ^ 1];
#pragma unroll
            for (int j = 0; j < 4; j++) {
                uint4 u = {f2tf(av[j].x), f2tf(av[j].y), f2tf(av[j].z), f2tf(av[j].w)};
                *(uint4*)(A + arow * AS_STRIDE + kh * 16 + j * 4) = u;
            }
#pragma unroll
            for (int i = 0; i < 4; i++) {
                uint4 u = {f2tf(bv[i].x), f2tf(bv[i].y), f2tf(bv[i].z), f2tf(bv[i].w)};
                *(uint4*)(B + (bwarp + i * 8) * BS_STRIDE + blane * 4) = u;
            }
        }
        __syncthreads();
    }

    // ---- epilogue (registers -> gmem), c0/c1 at row g, c2/c3 at row g+8
#pragma unroll
    for (int mt = 0; mt < 4; mt++) {
#pragma unroll
        for (int rr = 0; rr < 2; rr++) {
            int m   = wm * 64 + mt * 16 + g + rr * 8;
            int pos = row0 + m;
            if (pos >= cnt) continue;
#pragma unroll
            for (int nt = 0; nt < 4; nt++) {
                int n = col0 + wn * 32 + nt * 8 + 2 * t4;
                float v0 = acc[mt][nt][rr * 2 + 0] + Bias[e * NDIM + n];
                float v1 = acc[mt][nt][rr * 2 + 1] + Bias[e * NDIM + n + 1];
                if (!PHASE2) {
                    float2 o = {gelu_tanh(v0), gelu_tanh(v1)};
                    *(float2*)(g_h + (size_t)(off + pos) * F_DIM + n) = o;
                } else {
                    float2 o = {v0, v1};
                    *(float2*)(g_h2 + (size_t)(off + pos) * H_DIM + n) = o;
                }
            }
        }
    }
}

// ---------------- combine: out[t] = w0*h2[slot0] + w1*h2[slot1] --------------
__global__ __launch_bounds__(256) void combine_kernel(float* __restrict__ out) {
    int t = blockIdx.x;
    int c = threadIdx.x * 4;
    int e0 = g_pE[2 * t],     e1 = g_pE[2 * t + 1];
    int s0 = g_off[e0] + g_pP[2 * t];
    int s1 = g_off[e1] + g_pP[2 * t + 1];
    float w0 = g_pW[2 * t], w1 = g_pW[2 * t + 1];
    float4 a = *(const float4*)(g_h2 + (size_t)s0 * H_DIM + c);
    float4 b = *(const float4*)(g_h2 + (size_t)s1 * H_DIM + c);
    float4 o;
    o.x = w0 * a.x + w1 * b.x;
    o.y = w0 * a.y + w1 * b.y;
    o.z = w0 * a.z + w1 * b.z;
    o.w = w0 * a.w + w1 * b.w;
    *(float4*)(out + (size_t)t * H_DIM + c) = o;
}

// ---------------- launch ------------------------------------------------------
extern "C" void kernel_launch(void* const* d_in, const int* in_sizes, int n_in,
                              void* d_out, int out_size) {
    const float* x  = (const float*)d_in[0];  // [B,S,H]
    const float* w1 = (const float*)d_in[1];  // [E,H,F]
    const float* b1 = (const float*)d_in[2];  // [E,F]
    const float* w2 = (const float*)d_in[3];  // [E,F,H]
    const float* b2 = (const float*)d_in[4];  // [E,H]
    const float* rw = (const float*)d_in[5];  // [H,E]
    const float* rb = (const float*)d_in[6];  // [E]
    float* out = (float*)d_out;

    cudaFuncSetAttribute(moe_mma<false>, cudaFuncAttributeMaxDynamicSharedMemorySize,
                         SMEM_DYN);
    cudaFuncSetAttribute(moe_mma<true>, cudaFuncAttributeMaxDynamicSharedMemorySize,
                         SMEM_DYN);

    zero_counts_kernel<<<1, 32>>>();
    router_kernel<<<T_TOK / 8, 256>>>(x, rw, rb);
    scan_kernel<<<1, 32>>>();

    dim3 block(256);
    dim3 grid1(F_DIM / BN, T_TOK / BM, NE);  // 32 x 64 x 8
    dim3 grid2(H_DIM / BN, T_TOK / BM, NE);  //  8 x 64 x 8
    moe_mma<false><<<grid1, block, SMEM_DYN>>>(x, w1, b1);
    moe_mma<true ><<<grid2, block, SMEM_DYN>>>(nullptr, w2, b2);
    combine_kernel<<<T_TOK, 256>>>(out);
}

// round 6
// speedup vs baseline: 7.5016x; 1.4302x over previous
#include <cuda_runtime.h>
#include <math.h>
#include <stdint.h>

#define T_TOK 8192
#define H_DIM 1024
#define F_DIM 4096
#define NE    8
#define BM    128
#define BN    128
#define BK    32
#define DEPTH 3

// ---------------- device scratch (static, no runtime allocation) ------------
__device__ float g_h [(size_t)(2 * T_TOK + BM) * F_DIM];  // gelu(x@w1+b1), tf32-rounded
__device__ float g_h2[(size_t)(2 * T_TOK + BM) * H_DIM];  // (h@w2+b2) per slot
__device__ float g_w1t[(size_t)NE * H_DIM * F_DIM];       // tf32-rounded w1
__device__ float g_w2t[(size_t)NE * F_DIM * H_DIM];       // tf32-rounded w2
__device__ float g_xt [(size_t)T_TOK * H_DIM];            // tf32-rounded x
__device__ int   g_tok[NE * T_TOK];
__device__ int   g_cnt[NE];
__device__ int   g_off[NE];
__device__ int   g_pE[2 * T_TOK];
__device__ int   g_pP[2 * T_TOK];
__device__ float g_pW[2 * T_TOK];

// ---------------- helpers ----------------------------------------------------
__device__ __forceinline__ uint32_t f2tf(float f) {
    uint32_t u;
    asm("cvt.rna.tf32.f32 %0, %1;" : "=r"(u) : "f"(f));
    return u;
}
__device__ __forceinline__ float f2tf_f(float f) {
    return __uint_as_float(f2tf(f));
}
__device__ __forceinline__ void mma8(float* d, const uint32_t* a, const uint32_t* b) {
    asm volatile(
        "mma.sync.aligned.m16n8k8.row.col.f32.tf32.tf32.f32 "
        "{%0,%1,%2,%3}, {%4,%5,%6,%7}, {%8,%9}, {%0,%1,%2,%3};"
        : "+f"(d[0]), "+f"(d[1]), "+f"(d[2]), "+f"(d[3])
        : "r"(a[0]), "r"(a[1]), "r"(a[2]), "r"(a[3]), "r"(b[0]), "r"(b[1]));
}
__device__ __forceinline__ uint32_t smem_u32(const void* p) {
    uint32_t a;
    asm("{ .reg .u64 t; cvta.to.shared.u64 t, %1; cvt.u32.u64 %0, t; }" : "=r"(a) : "l"(p));
    return a;
}
__device__ __forceinline__ void cp16(uint32_t dst, const void* src, bool pred) {
    int sz = pred ? 16 : 0;
    asm volatile("cp.async.cg.shared.global [%0], [%1], 16, %2;"
                 :: "r"(dst), "l"(src), "r"(sz) : "memory");
}
__device__ __forceinline__ void cp_commit() {
    asm volatile("cp.async.commit_group;" ::: "memory");
}
template <int N>
__device__ __forceinline__ void cp_wait() {
    asm volatile("cp.async.wait_group %0;" :: "n"(N) : "memory");
}
__device__ __forceinline__ float gelu_tanh(float v) {
    float u = 0.7978845608028654f * (v + 0.044715f * v * v * v);
    return 0.5f * v * (1.0f + tanhf(u));
}

// ---------------- tf32 pre-round pass ----------------------------------------
__global__ __launch_bounds__(256) void round_tf32_kernel(const float* __restrict__ src,
                                                         float* __restrict__ dst,
                                                         size_t n4) {
    size_t stride = (size_t)gridDim.x * blockDim.x;
    for (size_t i = blockIdx.x * (size_t)blockDim.x + threadIdx.x; i < n4; i += stride) {
        float4 v = ((const float4*)src)[i];
        float4 o = {f2tf_f(v.x), f2tf_f(v.y), f2tf_f(v.z), f2tf_f(v.w)};
        ((float4*)dst)[i] = o;
    }
}

// ---------------- router ------------------------------------------------------
__global__ void zero_counts_kernel() {
    if (threadIdx.x < NE) g_cnt[threadIdx.x] = 0;
}
__global__ void scan_kernel() {
    if (threadIdx.x == 0) {
        int s = 0;
        for (int e = 0; e < NE; e++) { g_off[e] = s; s += g_cnt[e]; }
    }
}
__global__ __launch_bounds__(256) void router_kernel(const float* __restrict__ x,
                                                     const float* __restrict__ rw,
                                                     const float* __restrict__ rb) {
    int warp = threadIdx.x >> 5, lane = threadIdx.x & 31;
    int t = blockIdx.x * 8 + warp;
    if (t >= T_TOK) return;
    const float* xr = x + (size_t)t * H_DIM;
    float acc[NE];
#pragma unroll
    for (int e = 0; e < NE; e++) acc[e] = 0.f;
    for (int h = lane; h < H_DIM; h += 32) {
        float xv = xr[h];
        const float* wr = rw + h * NE;
#pragma unroll
        for (int e = 0; e < NE; e++) acc[e] += xv * wr[e];
    }
#pragma unroll
    for (int off = 16; off > 0; off >>= 1)
#pragma unroll
        for (int e = 0; e < NE; e++) acc[e] += __shfl_xor_sync(0xffffffffu, acc[e], off);
    if (lane == 0) {
#pragma unroll
        for (int e = 0; e < NE; e++) acc[e] += rb[e];
        int i1 = 0;
#pragma unroll
        for (int e = 1; e < NE; e++) if (acc[e] > acc[i1]) i1 = e;
        int i2 = -1;
#pragma unroll
        for (int e = 0; e < NE; e++) {
            if (e == i1) continue;
            if (i2 < 0 || acc[e] > acc[i2]) i2 = e;
        }
        float d   = acc[i2] - acc[i1];
        float w1p = 1.f / (1.f + expf(d));
        float w2p = 1.f - w1p;
        int p1 = atomicAdd(&g_cnt[i1], 1);
        g_tok[i1 * T_TOK + p1] = t;
        g_pE[2 * t] = i1; g_pP[2 * t] = p1; g_pW[2 * t] = w1p;
        int p2 = atomicAdd(&g_cnt[i2], 1);
        g_tok[i2 * T_TOK + p2] = t;
        g_pE[2 * t + 1] = i2; g_pP[2 * t + 1] = p2; g_pW[2 * t + 1] = w2p;
    }
}

// ---------------- tf32 mma.sync GEMM with cp.async ring ----------------------
#define AS_STRIDE 36
#define BS_STRIDE 136
#define AS_WORDS  (BM * AS_STRIDE)                   // 4608
#define BS_WORDS  (BK * BS_STRIDE)                   // 4352
#define STG_WORDS (AS_WORDS + BS_WORDS)              // 8960
#define SMEM_DYN  (DEPTH * STG_WORDS * 4)            // 107520 B

template <bool PHASE2>
__global__ __launch_bounds__(256, 2) void moe_mma(const float* __restrict__ X,
                                                  const float* __restrict__ W,
                                                  const float* __restrict__ Bias) {
    constexpr int KDIM   = PHASE2 ? F_DIM : H_DIM;
    constexpr int NDIM   = PHASE2 ? H_DIM : F_DIM;
    constexpr int STAGES = KDIM / BK;

    const int e    = blockIdx.z;
    const int cnt  = g_cnt[e];
    const int row0 = blockIdx.y * BM;
    if (row0 >= cnt) return;
    const int col0 = blockIdx.x * BN;
    const int off  = g_off[e];
    const float* Wexp = W + (size_t)e * KDIM * NDIM;

    extern __shared__ uint32_t smu[];
    __shared__ int toks_s[BM];
    const int tid = threadIdx.x;
    if (!PHASE2 && tid < BM) {
        int pos = row0 + tid;
        toks_s[tid] = (pos < cnt) ? g_tok[e * T_TOK + pos] : -1;
    }
    __syncthreads();

    // A loader: row = tid>>1 (0..127), khalf = tid&1 -> 4x16B per stage
    const int arow = tid >> 1, kh = tid & 1;
    const float* aptr;
    bool avalid = true;
    if (PHASE2) {
        aptr = g_h + (size_t)(off + row0 + arow) * F_DIM;
    } else {
        int tk = toks_s[arow];
        avalid = tk >= 0;
        aptr = avalid ? (X + (size_t)tk * H_DIM) : X;
    }
    // B loader: k = bwarp + i*8, 4 floats at n = blane*4 -> 4x16B per stage
    const int bwarp = tid >> 5, blane = tid & 31;
    const float* bbase = Wexp + (size_t)bwarp * NDIM + col0 + blane * 4;

    // per-thread smem word offsets inside a stage
    const uint32_t smem_base = smem_u32(smu);
    const uint32_t a_off = (uint32_t)(arow * AS_STRIDE + kh * 16) * 4u;
    const uint32_t b_off = (uint32_t)(AS_WORDS + bwarp * BS_STRIDE + blane * 4) * 4u;

    const int lane = tid & 31;
    const int g  = lane >> 2, t4 = lane & 3;
    const int wm = (tid >> 5) >> 2, wn = (tid >> 5) & 3;

    float acc[4][4][4];
#pragma unroll
    for (int mt = 0; mt < 4; mt++)
#pragma unroll
        for (int nt = 0; nt < 4; nt++)
#pragma unroll
            for (int r = 0; r < 4; r++) acc[mt][nt][r] = 0.f;

    // issue cp.async for stage t into ring slot t%DEPTH
    auto issue = [&](int t) {
        uint32_t sb = smem_base + (uint32_t)(t % DEPTH) * (STG_WORDS * 4u);
        int k0 = t * BK;
#pragma unroll
        for (int j = 0; j < 4; j++)
            cp16(sb + a_off + j * 16u, aptr + k0 + kh * 16 + j * 4, avalid);
#pragma unroll
        for (int i = 0; i < 4; i++)
            cp16(sb + b_off + (uint32_t)(i * 8 * BS_STRIDE) * 4u,
                 bbase + (size_t)(k0 + i * 8) * NDIM, true);
        cp_commit();
    };

    // prologue: stages 0..DEPTH-2 in flight
#pragma unroll
    for (int t = 0; t < DEPTH - 1; t++) issue(t);

    for (int s = 0; s < STAGES; s++) {
        cp_wait<DEPTH - 2>();        // stage s resident
        __syncthreads();             // + all warps done reading slot (s-1)%DEPTH
        if (s + DEPTH - 1 < STAGES) issue(s + DEPTH - 1);

        const uint32_t* SB = smu + (s % DEPTH) * STG_WORDS;
        const uint32_t* A = SB;
        const uint32_t* B = SB + AS_WORDS;
#pragma unroll
        for (int ks = 0; ks < 4; ks++) {
            uint32_t af[4][4], bf[4][2];
#pragma unroll
            for (int mt = 0; mt < 4; mt++) {
                const uint32_t* ap = A + (wm * 64 + mt * 16 + g) * AS_STRIDE + ks * 8 + t4;
                af[mt][0] = ap[0];
                af[mt][1] = ap[8 * AS_STRIDE];
                af[mt][2] = ap[4];
                af[mt][3] = ap[8 * AS_STRIDE + 4];
            }
#pragma unroll
            for (int nt = 0; nt < 4; nt++) {
                const uint32_t* bp = B + (ks * 8 + t4) * BS_STRIDE + wn * 32 + nt * 8 + g;
                bf[nt][0] = bp[0];
                bf[nt][1] = bp[4 * BS_STRIDE];
            }
#pragma unroll
            for (int mt = 0; mt < 4; mt++)
#pragma unroll
                for (int nt = 0; nt < 4; nt++) mma8(acc[mt][nt], af[mt], bf[nt]);
        }
    }

    // ---- epilogue: c0/c1 at row g, c2/c3 at row g+8, cols 2*t4 (+1)
#pragma unroll
    for (int mt = 0; mt < 4; mt++) {
#pragma unroll
        for (int rr = 0; rr < 2; rr++) {
            int m   = wm * 64 + mt * 16 + g + rr * 8;
            int pos = row0 + m;
            if (pos >= cnt) continue;
#pragma unroll
            for (int nt = 0; nt < 4; nt++) {
                int n = col0 + wn * 32 + nt * 8 + 2 * t4;
                float v0 = acc[mt][nt][rr * 2 + 0] + Bias[e * NDIM + n];
                float v1 = acc[mt][nt][rr * 2 + 1] + Bias[e * NDIM + n + 1];
                if (!PHASE2) {
                    // store tf32-rounded gelu so phase2 can cp.async raw
                    float2 o = {f2tf_f(gelu_tanh(v0)), f2tf_f(gelu_tanh(v1))};
                    *(float2*)(g_h + (size_t)(off + pos) * F_DIM + n) = o;
                } else {
                    float2 o = {v0, v1};
                    *(float2*)(g_h2 + (size_t)(off + pos) * H_DIM + n) = o;
                }
            }
        }
    }
}

// ---------------- combine: out[t] = w0*h2[slot0] + w1*h2[slot1] --------------
__global__ __launch_bounds__(256) void combine_kernel(float* __restrict__ out) {
    int t = blockIdx.x;
    int c = threadIdx.x * 4;
    int e0 = g_pE[2 * t],     e1 = g_pE[2 * t + 1];
    int s0 = g_off[e0] + g_pP[2 * t];
    int s1 = g_off[e1] + g_pP[2 * t + 1];
    float w0 = g_pW[2 * t], w1 = g_pW[2 * t + 1];
    float4 a = *(const float4*)(g_h2 + (size_t)s0 * H_DIM + c);
    float4 b = *(const float4*)(g_h2 + (size_t)s1 * H_DIM + c);
    float4 o;
    o.x = w0 * a.x + w1 * b.x;
    o.y = w0 * a.y + w1 * b.y;
    o.z = w0 * a.z + w1 * b.z;
    o.w = w0 * a.w + w1 * b.w;
    *(float4*)(out + (size_t)t * H_DIM + c) = o;
}

// ---------------- launch ------------------------------------------------------
extern "C" void kernel_launch(void* const* d_in, const int* in_sizes, int n_in,
                              void* d_out, int out_size) {
    const float* x  = (const float*)d_in[0];  // [B,S,H]
    const float* w1 = (const float*)d_in[1];  // [E,H,F]
    const float* b1 = (const float*)d_in[2];  // [E,F]
    const float* w2 = (const float*)d_in[3];  // [E,F,H]
    const float* b2 = (const float*)d_in[4];  // [E,H]
    const float* rw = (const float*)d_in[5];  // [H,E]
    const float* rb = (const float*)d_in[6];  // [E]
    float* out = (float*)d_out;

    cudaFuncSetAttribute(moe_mma<false>, cudaFuncAttributeMaxDynamicSharedMemorySize,
                         SMEM_DYN);
    cudaFuncSetAttribute(moe_mma<true>, cudaFuncAttributeMaxDynamicSharedMemorySize,
                         SMEM_DYN);

    // resolve device-global scratch addresses (host side, graph-capturable)
    static float *p_w1t = nullptr, *p_w2t = nullptr, *p_xt = nullptr;
    if (!p_w1t) {
        cudaGetSymbolAddress((void**)&p_w1t, g_w1t);
        cudaGetSymbolAddress((void**)&p_w2t, g_w2t);
        cudaGetSymbolAddress((void**)&p_xt, g_xt);
    }

    zero_counts_kernel<<<1, 32>>>();
    router_kernel<<<T_TOK / 8, 256>>>(x, rw, rb);
    scan_kernel<<<1, 32>>>();

    round_tf32_kernel<<<4096, 256>>>(w1, p_w1t, (size_t)NE * H_DIM * F_DIM / 4);
    round_tf32_kernel<<<4096, 256>>>(w2, p_w2t, (size_t)NE * F_DIM * H_DIM / 4);
    round_tf32_kernel<<<1024, 256>>>(x, p_xt, (size_t)T_TOK * H_DIM / 4);

    dim3 block(256);
    dim3 grid1(F_DIM / BN, T_TOK / BM, NE);  // 32 x 64 x 8
    dim3 grid2(H_DIM / BN, T_TOK / BM, NE);  //  8 x 64 x 8
    moe_mma<false><<<grid1, block, SMEM_DYN>>>(p_xt, p_w1t, b1);
    moe_mma<true ><<<grid2, block, SMEM_DYN>>>(nullptr, p_w2t, b2);
    combine_kernel<<<T_TOK, 256>>>(out);
}

// round 7
// speedup vs baseline: 7.8065x; 1.0406x over previous
#include <cuda_runtime.h>
#include <math.h>
#include <stdint.h>

#define T_TOK 8192
#define H_DIM 1024
#define F_DIM 4096
#define NE    8
#define BM    128
#define BN    128
#define BK    32
#define DEPTH 3

// ---------------- device scratch (static, no runtime allocation) ------------
__device__ float g_h [(size_t)(2 * T_TOK + BM) * F_DIM];  // gelu(x@w1+b1), tf32-rounded
__device__ float g_h2[(size_t)(2 * T_TOK + BM) * H_DIM];  // (h@w2+b2) per slot
__device__ float g_w1t[(size_t)NE * H_DIM * F_DIM];       // tf32-rounded w1
__device__ float g_w2t[(size_t)NE * F_DIM * H_DIM];       // tf32-rounded w2
__device__ float g_xt [(size_t)T_TOK * H_DIM];            // tf32-rounded x
__device__ int   g_tok[NE * T_TOK];
__device__ int   g_cnt[NE];
__device__ int   g_off[NE];
__device__ int   g_pE[2 * T_TOK];
__device__ int   g_pP[2 * T_TOK];
__device__ float g_pW[2 * T_TOK];

// ---------------- helpers ----------------------------------------------------
__device__ __forceinline__ uint32_t f2tf(float f) {
    uint32_t u;
    asm("cvt.rna.tf32.f32 %0, %1;" : "=r"(u) : "f"(f));
    return u;
}
__device__ __forceinline__ float f2tf_f(float f) { return __uint_as_float(f2tf(f)); }
__device__ __forceinline__ void mma8(float* d, const uint32_t* a, const uint32_t* b) {
    asm volatile(
        "mma.sync.aligned.m16n8k8.row.col.f32.tf32.tf32.f32 "
        "{%0,%1,%2,%3}, {%4,%5,%6,%7}, {%8,%9}, {%0,%1,%2,%3};"
        : "+f"(d[0]), "+f"(d[1]), "+f"(d[2]), "+f"(d[3])
        : "r"(a[0]), "r"(a[1]), "r"(a[2]), "r"(a[3]), "r"(b[0]), "r"(b[1]));
}
__device__ __forceinline__ void ldm4(uint32_t* r, uint32_t addr) {
    asm volatile("ldmatrix.sync.aligned.m8n8.x4.shared.b16 {%0,%1,%2,%3}, [%4];"
                 : "=r"(r[0]), "=r"(r[1]), "=r"(r[2]), "=r"(r[3]) : "r"(addr));
}
__device__ __forceinline__ uint32_t smem_u32(const void* p) {
    uint32_t a;
    asm("{ .reg .u64 t; cvta.to.shared.u64 t, %1; cvt.u32.u64 %0, t; }" : "=r"(a) : "l"(p));
    return a;
}
__device__ __forceinline__ void cp16(uint32_t dst, const void* src, bool pred) {
    int sz = pred ? 16 : 0;
    asm volatile("cp.async.cg.shared.global [%0], [%1], 16, %2;"
                 :: "r"(dst), "l"(src), "r"(sz) : "memory");
}
__device__ __forceinline__ void cp_commit() {
    asm volatile("cp.async.commit_group;" ::: "memory");
}
template <int N>
__device__ __forceinline__ void cp_wait() {
    asm volatile("cp.async.wait_group %0;" :: "n"(N) : "memory");
}
__device__ __forceinline__ float gelu_tanh(float v) {
    float u = 0.7978845608028654f * (v + 0.044715f * v * v * v);
    return 0.5f * v * (1.0f + tanhf(u));
}

// ---------------- tf32 pre-round pass ----------------------------------------
__global__ __launch_bounds__(256) void round_tf32_kernel(const float* __restrict__ src,
                                                         float* __restrict__ dst,
                                                         size_t n4) {
    size_t stride = (size_t)gridDim.x * blockDim.x;
    for (size_t i = blockIdx.x * (size_t)blockDim.x + threadIdx.x; i < n4; i += stride) {
        float4 v = ((const float4*)src)[i];
        float4 o = {f2tf_f(v.x), f2tf_f(v.y), f2tf_f(v.z), f2tf_f(v.w)};
        ((float4*)dst)[i] = o;
    }
}

// ---------------- router ------------------------------------------------------
__global__ void zero_counts_kernel() {
    if (threadIdx.x < NE) g_cnt[threadIdx.x] = 0;
}
__global__ void scan_kernel() {
    if (threadIdx.x == 0) {
        int s = 0;
        for (int e = 0; e < NE; e++) { g_off[e] = s; s += g_cnt[e]; }
    }
}
__global__ __launch_bounds__(256) void router_kernel(const float* __restrict__ x,
                                                     const float* __restrict__ rw,
                                                     const float* __restrict__ rb) {
    int warp = threadIdx.x >> 5, lane = threadIdx.x & 31;
    int t = blockIdx.x * 8 + warp;
    if (t >= T_TOK) return;
    const float* xr = x + (size_t)t * H_DIM;
    float acc[NE];
#pragma unroll
    for (int e = 0; e < NE; e++) acc[e] = 0.f;
    for (int h = lane; h < H_DIM; h += 32) {
        float xv = xr[h];
        const float* wr = rw + h * NE;
#pragma unroll
        for (int e = 0; e < NE; e++) acc[e] += xv * wr[e];
    }
#pragma unroll
    for (int off = 16; off > 0; off >>= 1)
#pragma unroll
        for (int e = 0; e < NE; e++) acc[e] += __shfl_xor_sync(0xffffffffu, acc[e], off);
    if (lane == 0) {
#pragma unroll
        for (int e = 0; e < NE; e++) acc[e] += rb[e];
        int i1 = 0;
#pragma unroll
        for (int e = 1; e < NE; e++) if (acc[e] > acc[i1]) i1 = e;
        int i2 = -1;
#pragma unroll
        for (int e = 0; e < NE; e++) {
            if (e == i1) continue;
            if (i2 < 0 || acc[e] > acc[i2]) i2 = e;
        }
        float d   = acc[i2] - acc[i1];
        float w1p = 1.f / (1.f + expf(d));
        float w2p = 1.f - w1p;
        int p1 = atomicAdd(&g_cnt[i1], 1);
        g_tok[i1 * T_TOK + p1] = t;
        g_pE[2 * t] = i1; g_pP[2 * t] = p1; g_pW[2 * t] = w1p;
        int p2 = atomicAdd(&g_cnt[i2], 1);
        g_tok[i2 * T_TOK + p2] = t;
        g_pE[2 * t + 1] = i2; g_pP[2 * t + 1] = p2; g_pW[2 * t + 1] = w2p;
    }
}

// ---------------- tf32 mma.sync GEMM with cp.async ring + ldmatrix -----------
#define AS_STRIDE 36
#define BS_STRIDE 136
#define AS_WORDS  (BM * AS_STRIDE)                   // 4608
#define BS_WORDS  (BK * BS_STRIDE)                   // 4352
#define STG_WORDS (AS_WORDS + BS_WORDS)              // 8960
#define STG_BYTES (STG_WORDS * 4)
#define SMEM_DYN  (DEPTH * STG_BYTES)                // 107520 B

template <bool PHASE2>
__global__ __launch_bounds__(256, 2) void moe_mma(const float* __restrict__ X,
                                                  const float* __restrict__ W,
                                                  const float* __restrict__ Bias) {
    constexpr int KDIM   = PHASE2 ? F_DIM : H_DIM;
    constexpr int NDIM   = PHASE2 ? H_DIM : F_DIM;
    constexpr int STAGES = KDIM / BK;

    const int e    = blockIdx.z;
    const int cnt  = g_cnt[e];
    const int row0 = blockIdx.y * BM;
    if (row0 >= cnt) return;
    const int col0 = blockIdx.x * BN;
    const int off  = g_off[e];
    const float* Wexp = W + (size_t)e * KDIM * NDIM;

    extern __shared__ uint32_t smu[];
    __shared__ int toks_s[BM];
    const int tid = threadIdx.x;
    if (!PHASE2 && tid < BM) {
        int pos = row0 + tid;
        toks_s[tid] = (pos < cnt) ? g_tok[e * T_TOK + pos] : -1;
    }
    __syncthreads();

    // A loader: row = tid>>1 (0..127), khalf = tid&1 -> 4x16B per stage
    const int arow = tid >> 1, kh = tid & 1;
    const float* aptr;
    bool avalid = true;
    if (PHASE2) {
        aptr = g_h + (size_t)(off + row0 + arow) * F_DIM;
    } else {
        int tk = toks_s[arow];
        avalid = tk >= 0;
        aptr = avalid ? (X + (size_t)tk * H_DIM) : X;
    }
    // B loader: k = bwarp + i*8, 4 floats at n = blane*4 -> 4x16B per stage
    const int bwarp = tid >> 5, blane = tid & 31;
    const float* bbase = Wexp + (size_t)bwarp * NDIM + col0 + blane * 4;

    const uint32_t smem_base = smem_u32(smu);
    const uint32_t a_off = (uint32_t)(arow * AS_STRIDE + kh * 16) * 4u;
    const uint32_t b_off = (uint32_t)(AS_WORDS + bwarp * BS_STRIDE + blane * 4) * 4u;

    const int lane = tid & 31;
    const int g  = lane >> 2, t4 = lane & 3;
    const int wm = (tid >> 5) >> 2, wn = (tid >> 5) & 3;

    // ldmatrix lane->address mapping: matrices M0..M3 = a0..a3
    const int rowadj = lane & 15;            // row within 16-row tile
    const int kadj   = (lane >> 4) * 4;      // +4 words for M2/M3 (k+4)
    uint32_t a_frag_off[4];                  // byte offset of mt's frag base in stage
#pragma unroll
    for (int mt = 0; mt < 4; mt++)
        a_frag_off[mt] =
            (uint32_t)((wm * 64 + mt * 16 + rowadj) * AS_STRIDE + kadj) * 4u;
    // B fragment word offsets in stage (bank-conflict-free: (8*t4+g)%32 bijective)
    const uint32_t b_frag0 = (uint32_t)(AS_WORDS + t4 * BS_STRIDE + wn * 32 + g);

    float acc[4][4][4];
#pragma unroll
    for (int mt = 0; mt < 4; mt++)
#pragma unroll
        for (int nt = 0; nt < 4; nt++)
#pragma unroll
            for (int r = 0; r < 4; r++) acc[mt][nt][r] = 0.f;

    auto issue = [&](int t) {
        uint32_t sb = smem_base + (uint32_t)(t % DEPTH) * STG_BYTES;
        int k0 = t * BK;
#pragma unroll
        for (int j = 0; j < 4; j++)
            cp16(sb + a_off + j * 16u, aptr + k0 + kh * 16 + j * 4, avalid);
#pragma unroll
        for (int i = 0; i < 4; i++)
            cp16(sb + b_off + (uint32_t)(i * 8 * BS_STRIDE) * 4u,
                 bbase + (size_t)(k0 + i * 8) * NDIM, true);
        cp_commit();
    };

#pragma unroll
    for (int t = 0; t < DEPTH - 1; t++) issue(t);

    for (int s = 0; s < STAGES; s++) {
        cp_wait<DEPTH - 2>();
        __syncthreads();
        if (s + DEPTH - 1 < STAGES) issue(s + DEPTH - 1);

        const uint32_t sslot = smem_base + (uint32_t)(s % DEPTH) * STG_BYTES;
        const uint32_t* SB = smu + (s % DEPTH) * STG_WORDS;
#pragma unroll
        for (int ks = 0; ks < 4; ks++) {
            uint32_t af[4][4], bf[4][2];
#pragma unroll
            for (int mt = 0; mt < 4; mt++)
                ldm4(af[mt], sslot + a_frag_off[mt] + (uint32_t)ks * 32u);
#pragma unroll
            for (int nt = 0; nt < 4; nt++) {
                const uint32_t* bp = SB + b_frag0 + ks * 8 * BS_STRIDE + nt * 8;
                bf[nt][0] = bp[0];
                bf[nt][1] = bp[4 * BS_STRIDE];
            }
#pragma unroll
            for (int mt = 0; mt < 4; mt++)
#pragma unroll
                for (int nt = 0; nt < 4; nt++) mma8(acc[mt][nt], af[mt], bf[nt]);
        }
    }

    // ---- epilogue: c0/c1 at row g, c2/c3 at row g+8, cols 2*t4 (+1)
#pragma unroll
    for (int mt = 0; mt < 4; mt++) {
#pragma unroll
        for (int rr = 0; rr < 2; rr++) {
            int m   = wm * 64 + mt * 16 + g + rr * 8;
            int pos = row0 + m;
            if (pos >= cnt) continue;
#pragma unroll
            for (int nt = 0; nt < 4; nt++) {
                int n = col0 + wn * 32 + nt * 8 + 2 * t4;
                float v0 = acc[mt][nt][rr * 2 + 0] + Bias[e * NDIM + n];
                float v1 = acc[mt][nt][rr * 2 + 1] + Bias[e * NDIM + n + 1];
                if (!PHASE2) {
                    float2 o = {f2tf_f(gelu_tanh(v0)), f2tf_f(gelu_tanh(v1))};
                    *(float2*)(g_h + (size_t)(off + pos) * F_DIM + n) = o;
                } else {
                    float2 o = {v0, v1};
                    *(float2*)(g_h2 + (size_t)(off + pos) * H_DIM + n) = o;
                }
            }
        }
    }
}

// ---------------- combine: out[t] = w0*h2[slot0] + w1*h2[slot1] --------------
__global__ __launch_bounds__(256) void combine_kernel(float* __restrict__ out) {
    int t = blockIdx.x;
    int c = threadIdx.x * 4;
    int e0 = g_pE[2 * t],     e1 = g_pE[2 * t + 1];
    int s0 = g_off[e0] + g_pP[2 * t];
    int s1 = g_off[e1] + g_pP[2 * t + 1];
    float w0 = g_pW[2 * t], w1 = g_pW[2 * t + 1];
    float4 a = *(const float4*)(g_h2 + (size_t)s0 * H_DIM + c);
    float4 b = *(const float4*)(g_h2 + (size_t)s1 * H_DIM + c);
    float4 o;
    o.x = w0 * a.x + w1 * b.x;
    o.y = w0 * a.y + w1 * b.y;
    o.z = w0 * a.z + w1 * b.z;
    o.w = w0 * a.w + w1 * b.w;
    *(float4*)(out + (size_t)t * H_DIM + c) = o;
}

// ---------------- launch ------------------------------------------------------
extern "C" void kernel_launch(void* const* d_in, const int* in_sizes, int n_in,
                              void* d_out, int out_size) {
    const float* x  = (const float*)d_in[0];  // [B,S,H]
    const float* w1 = (const float*)d_in[1];  // [E,H,F]
    const float* b1 = (const float*)d_in[2];  // [E,F]
    const float* w2 = (const float*)d_in[3];  // [E,F,H]
    const float* b2 = (const float*)d_in[4];  // [E,H]
    const float* rw = (const float*)d_in[5];  // [H,E]
    const float* rb = (const float*)d_in[6];  // [E]
    float* out = (float*)d_out;

    cudaFuncSetAttribute(moe_mma<false>, cudaFuncAttributeMaxDynamicSharedMemorySize,
                         SMEM_DYN);
    cudaFuncSetAttribute(moe_mma<true>, cudaFuncAttributeMaxDynamicSharedMemorySize,
                         SMEM_DYN);

    static float *p_w1t = nullptr, *p_w2t = nullptr, *p_xt = nullptr;
    if (!p_w1t) {
        cudaGetSymbolAddress((void**)&p_w1t, g_w1t);
        cudaGetSymbolAddress((void**)&p_w2t, g_w2t);
        cudaGetSymbolAddress((void**)&p_xt, g_xt);
    }

    zero_counts_kernel<<<1, 32>>>();
    router_kernel<<<T_TOK / 8, 256>>>(x, rw, rb);
    scan_kernel<<<1, 32>>>();

    round_tf32_kernel<<<4096, 256>>>(w1, p_w1t, (size_t)NE * H_DIM * F_DIM / 4);
    round_tf32_kernel<<<4096, 256>>>(w2, p_w2t, (size_t)NE * F_DIM * H_DIM / 4);
    round_tf32_kernel<<<1024, 256>>>(x, p_xt, (size_t)T_TOK * H_DIM / 4);

    dim3 block(256);
    dim3 grid1(F_DIM / BN, T_TOK / BM, NE);  // 32 x 64 x 8
    dim3 grid2(H_DIM / BN, T_TOK / BM, NE);  //  8 x 64 x 8
    moe_mma<false><<<grid1, block, SMEM_DYN>>>(p_xt, p_w1t, b1);
    moe_mma<true ><<<grid2, block, SMEM_DYN>>>(nullptr, p_w2t, b2);
    combine_kernel<<<T_TOK, 256>>>(out);
}

// round 9
// speedup vs baseline: 8.6778x; 1.1116x over previous
#include <cuda_runtime.h>
#include <cuda_fp16.h>
#include <math.h>
#include <stdint.h>

#define T_TOK 8192
#define H_DIM 1024
#define F_DIM 4096
#define NE    8
#define BM    128
#define BN    128
#define BK    32
#define DEPTH 3

// ---------------- device scratch (static, no runtime allocation) ------------
__device__ __half g_h  [(size_t)(2 * T_TOK + BM) * F_DIM];  // gelu(x@w1+b1) fp16
__device__ float  g_h2 [(size_t)(2 * T_TOK + BM) * H_DIM];  // (h@w2+b2) fp32
__device__ __half g_w1h[(size_t)NE * H_DIM * F_DIM];        // fp16 w1
__device__ __half g_w2h[(size_t)NE * F_DIM * H_DIM];        // fp16 w2
__device__ __half g_xh [(size_t)T_TOK * H_DIM];             // fp16 x
__device__ int    g_tok[NE * T_TOK];
__device__ int    g_cnt[NE];
__device__ int    g_off[NE];
__device__ int    g_pE[2 * T_TOK];
__device__ int    g_pP[2 * T_TOK];
__device__ float  g_pW[2 * T_TOK];

// ---------------- helpers ----------------------------------------------------
__device__ __forceinline__ void mma16(float* d, const uint32_t* a, const uint32_t* b) {
    asm volatile(
        "mma.sync.aligned.m16n8k16.row.col.f32.f16.f16.f32 "
        "{%0,%1,%2,%3}, {%4,%5,%6,%7}, {%8,%9}, {%0,%1,%2,%3};"
        : "+f"(d[0]), "+f"(d[1]), "+f"(d[2]), "+f"(d[3])
        : "r"(a[0]), "r"(a[1]), "r"(a[2]), "r"(a[3]), "r"(b[0]), "r"(b[1]));
}
__device__ __forceinline__ void ldm4(uint32_t* r, uint32_t addr) {
    asm volatile("ldmatrix.sync.aligned.m8n8.x4.shared.b16 {%0,%1,%2,%3}, [%4];"
                 : "=r"(r[0]), "=r"(r[1]), "=r"(r[2]), "=r"(r[3]) : "r"(addr));
}
__device__ __forceinline__ void ldm4t(uint32_t* r, uint32_t addr) {
    asm volatile("ldmatrix.sync.aligned.m8n8.x4.trans.shared.b16 {%0,%1,%2,%3}, [%4];"
                 : "=r"(r[0]), "=r"(r[1]), "=r"(r[2]), "=r"(r[3]) : "r"(addr));
}
__device__ __forceinline__ uint32_t smem_u32(const void* p) {
    uint32_t a;
    asm("{ .reg .u64 t; cvta.to.shared.u64 t, %1; cvt.u32.u64 %0, t; }" : "=r"(a) : "l"(p));
    return a;
}
__device__ __forceinline__ void cp16(uint32_t dst, const void* src, bool pred) {
    int sz = pred ? 16 : 0;
    asm volatile("cp.async.cg.shared.global [%0], [%1], 16, %2;"
                 :: "r"(dst), "l"(src), "r"(sz) : "memory");
}
__device__ __forceinline__ void cp_commit() {
    asm volatile("cp.async.commit_group;" ::: "memory");
}
template <int N>
__device__ __forceinline__ void cp_wait() {
    asm volatile("cp.async.wait_group %0;" :: "n"(N) : "memory");
}
__device__ __forceinline__ float gelu_tanh(float v) {
    float u = 0.7978845608028654f * (v + 0.044715f * v * v * v);
    return 0.5f * v * (1.0f + tanhf(u));
}

// ---------------- fp32 -> fp16 convert pass ----------------------------------
__global__ __launch_bounds__(256) void to_half_kernel(const float* __restrict__ src,
                                                      __half* __restrict__ dst,
                                                      size_t n8) {
    size_t stride = (size_t)gridDim.x * blockDim.x;
    for (size_t i = blockIdx.x * (size_t)blockDim.x + threadIdx.x; i < n8; i += stride) {
        float4 v0 = ((const float4*)src)[2 * i];
        float4 v1 = ((const float4*)src)[2 * i + 1];
        __half2 h0 = __floats2half2_rn(v0.x, v0.y);
        __half2 h1 = __floats2half2_rn(v0.z, v0.w);
        __half2 h2 = __floats2half2_rn(v1.x, v1.y);
        __half2 h3 = __floats2half2_rn(v1.z, v1.w);
        uint4 o = {*(uint32_t*)&h0, *(uint32_t*)&h1, *(uint32_t*)&h2, *(uint32_t*)&h3};
        ((uint4*)dst)[i] = o;
    }
}

// ---------------- router ------------------------------------------------------
__global__ void zero_counts_kernel() {
    if (threadIdx.x < NE) g_cnt[threadIdx.x] = 0;
}
__global__ void scan_kernel() {
    if (threadIdx.x == 0) {
        int s = 0;
        for (int e = 0; e < NE; e++) { g_off[e] = s; s += g_cnt[e]; }
    }
}
__global__ __launch_bounds__(256) void router_kernel(const float* __restrict__ x,
                                                     const float* __restrict__ rw,
                                                     const float* __restrict__ rb) {
    int warp = threadIdx.x >> 5, lane = threadIdx.x & 31;
    int t = blockIdx.x * 8 + warp;
    if (t >= T_TOK) return;
    const float* xr = x + (size_t)t * H_DIM;
    float acc[NE];
#pragma unroll
    for (int e = 0; e < NE; e++) acc[e] = 0.f;
    for (int h = lane; h < H_DIM; h += 32) {
        float xv = xr[h];
        const float* wr = rw + h * NE;
#pragma unroll
        for (int e = 0; e < NE; e++) acc[e] += xv * wr[e];
    }
#pragma unroll
    for (int off = 16; off > 0; off >>= 1)
#pragma unroll
        for (int e = 0; e < NE; e++) acc[e] += __shfl_xor_sync(0xffffffffu, acc[e], off);
    if (lane == 0) {
#pragma unroll
        for (int e = 0; e < NE; e++) acc[e] += rb[e];
        int i1 = 0;
#pragma unroll
        for (int e = 1; e < NE; e++) if (acc[e] > acc[i1]) i1 = e;
        int i2 = -1;
#pragma unroll
        for (int e = 0; e < NE; e++) {
            if (e == i1) continue;
            if (i2 < 0 || acc[e] > acc[i2]) i2 = e;
        }
        float d   = acc[i2] - acc[i1];
        float w1p = 1.f / (1.f + expf(d));
        float w2p = 1.f - w1p;
        int p1 = atomicAdd(&g_cnt[i1], 1);
        g_tok[i1 * T_TOK + p1] = t;
        g_pE[2 * t] = i1; g_pP[2 * t] = p1; g_pW[2 * t] = w1p;
        int p2 = atomicAdd(&g_cnt[i2], 1);
        g_tok[i2 * T_TOK + p2] = t;
        g_pE[2 * t + 1] = i2; g_pP[2 * t + 1] = p2; g_pW[2 * t + 1] = w2p;
    }
}

// ---------------- fp16 mma.sync GEMM with cp.async ring ----------------------
// A smem: 128 rows x 32 half, row stride 80B -> ldmatrix conflict-free
// B smem: 32 k-rows x 128 half, row stride 272B -> ldm.trans conflict-free
#define A_STRIDE_W 20
#define B_STRIDE_W 68
#define A_WORDS  (BM * A_STRIDE_W)                  // 2560
#define B_WORDS  (BK * B_STRIDE_W)                  // 2176
#define A_BYTES  (A_WORDS * 4)                      // 10240
#define STG_WORDS (A_WORDS + B_WORDS)               // 4736
#define STG_BYTES (STG_WORDS * 4)                   // 18944
#define SMEM_DYN  (DEPTH * STG_BYTES)               // 56832 B

template <bool PHASE2>
__global__ __launch_bounds__(256, 2) void moe_mma(const __half* __restrict__ X,
                                                  const __half* __restrict__ W,
                                                  const float* __restrict__ Bias) {
    constexpr int KDIM   = PHASE2 ? F_DIM : H_DIM;
    constexpr int NDIM   = PHASE2 ? H_DIM : F_DIM;
    constexpr int STAGES = KDIM / BK;

    const int e    = blockIdx.z;
    const int cnt  = g_cnt[e];
    const int row0 = blockIdx.y * BM;
    if (row0 >= cnt) return;
    const int col0 = blockIdx.x * BN;
    const int off  = g_off[e];
    const __half* Wexp = W + (size_t)e * KDIM * NDIM;

    extern __shared__ uint32_t smu[];
    __shared__ int toks_s[BM];
    const int tid = threadIdx.x;
    if (!PHASE2 && tid < BM) {
        int pos = row0 + tid;
        toks_s[tid] = (pos < cnt) ? g_tok[e * T_TOK + pos] : -1;
    }
    __syncthreads();

    // A loader: row = tid&127, khalf = tid>>7 -> 2x16B per stage (8KB total)
    const int arow = tid & 127, akh = tid >> 7;
    const __half* aptr;
    bool avalid = true;
    if (PHASE2) {
        aptr = g_h + (size_t)(off + row0 + arow) * F_DIM;
    } else {
        int tk = toks_s[arow];
        avalid = tk >= 0;
        aptr = avalid ? (X + (size_t)tk * H_DIM) : X;
    }
    // B loader: krow = tid>>4 (0..15, +16 for 2nd), chunk = tid&15 (16B x 16 = 256B row)
    // 2 cp16/thread = 8KB total  (round-8 bug: only half the tile was loaded)
    const int bk = tid >> 4, bc = tid & 15;
    const __half* bbase = Wexp + (size_t)bk * NDIM + col0 + bc * 8;

    const uint32_t smem_base = smem_u32(smu);
    const uint32_t a_off = (uint32_t)(arow * 80 + akh * 32);
    const uint32_t b_off = (uint32_t)(A_BYTES + bk * 272 + bc * 16);

    const int lane = tid & 31;
    const int g  = lane >> 2, t4 = lane & 3;
    const int wm = (tid >> 5) >> 2, wn = (tid >> 5) & 3;

    // A fragment base (ldmatrix x4): row = lane&15, +16B for k-high half
    uint32_t a_frag_off[4];
#pragma unroll
    for (int mt = 0; mt < 4; mt++)
        a_frag_off[mt] =
            (uint32_t)((wm * 64 + mt * 16 + (lane & 15)) * 80 + (lane >> 4) * 16);
    // B fragment base (ldmatrix x4 trans): krow = (lane&7) + ((lane>>3)&1)*8
    uint32_t b_frag_off[2];
#pragma unroll
    for (int ntp = 0; ntp < 2; ntp++)
        b_frag_off[ntp] = (uint32_t)(A_BYTES +
            ((lane & 7) + ((lane >> 3) & 1) * 8) * 272 +
            wn * 64 + ntp * 32 + (lane >> 4) * 16);

    float acc[4][4][4];
#pragma unroll
    for (int mt = 0; mt < 4; mt++)
#pragma unroll
        for (int nt = 0; nt < 4; nt++)
#pragma unroll
            for (int r = 0; r < 4; r++) acc[mt][nt][r] = 0.f;

    auto issue = [&](int t) {
        uint32_t sb = smem_base + (uint32_t)(t % DEPTH) * STG_BYTES;
        int k0 = t * BK;
        cp16(sb + a_off,       aptr + k0 + akh * 16,     avalid);
        cp16(sb + a_off + 16u, aptr + k0 + akh * 16 + 8, avalid);
        cp16(sb + b_off,                bbase + (size_t)k0 * NDIM,        true);
        cp16(sb + b_off + 16u * 272u,   bbase + (size_t)(k0 + 16) * NDIM, true);
        cp_commit();
    };

#pragma unroll
    for (int t = 0; t < DEPTH - 1; t++) issue(t);

    for (int s = 0; s < STAGES; s++) {
        cp_wait<DEPTH - 2>();
        __syncthreads();
        if (s + DEPTH - 1 < STAGES) issue(s + DEPTH - 1);

        const uint32_t sslot = smem_base + (uint32_t)(s % DEPTH) * STG_BYTES;
#pragma unroll
        for (int ks = 0; ks < 2; ks++) {          // two k16 steps per BK=32
            uint32_t af[4][4], bf[2][4];
#pragma unroll
            for (int mt = 0; mt < 4; mt++)
                ldm4(af[mt], sslot + a_frag_off[mt] + (uint32_t)ks * 32u);
#pragma unroll
            for (int ntp = 0; ntp < 2; ntp++)
                ldm4t(bf[ntp], sslot + b_frag_off[ntp] + (uint32_t)ks * 4352u);
#pragma unroll
            for (int mt = 0; mt < 4; mt++)
#pragma unroll
                for (int ntp = 0; ntp < 2; ntp++) {
                    mma16(acc[mt][2 * ntp],     af[mt], &bf[ntp][0]);
                    mma16(acc[mt][2 * ntp + 1], af[mt], &bf[ntp][2]);
                }
        }
    }

    // ---- epilogue: c0/c1 at row g, c2/c3 at row g+8, cols 2*t4 (+1)
#pragma unroll
    for (int mt = 0; mt < 4; mt++) {
#pragma unroll
        for (int rr = 0; rr < 2; rr++) {
            int m   = wm * 64 + mt * 16 + g + rr * 8;
            int pos = row0 + m;
            if (pos >= cnt) continue;
#pragma unroll
            for (int nt = 0; nt < 4; nt++) {
                int n = col0 + wn * 32 + nt * 8 + 2 * t4;
                float v0 = acc[mt][nt][rr * 2 + 0] + Bias[e * NDIM + n];
                float v1 = acc[mt][nt][rr * 2 + 1] + Bias[e * NDIM + n + 1];
                if (!PHASE2) {
                    __half2 o = __floats2half2_rn(gelu_tanh(v0), gelu_tanh(v1));
                    *(uint32_t*)(g_h + (size_t)(off + pos) * F_DIM + n) =
                        *(uint32_t*)&o;
                } else {
                    float2 o = {v0, v1};
                    *(float2*)(g_h2 + (size_t)(off + pos) * H_DIM + n) = o;
                }
            }
        }
    }
}

// ---------------- combine: out[t] = w0*h2[slot0] + w1*h2[slot1] --------------
__global__ __launch_bounds__(256) void combine_kernel(float* __restrict__ out) {
    int t = blockIdx.x;
    int c = threadIdx.x * 4;
    int e0 = g_pE[2 * t],     e1 = g_pE[2 * t + 1];
    int s0 = g_off[e0] + g_pP[2 * t];
    int s1 = g_off[e1] + g_pP[2 * t + 1];
    float w0 = g_pW[2 * t], w1 = g_pW[2 * t + 1];
    float4 a = *(const float4*)(g_h2 + (size_t)s0 * H_DIM + c);
    float4 b = *(const float4*)(g_h2 + (size_t)s1 * H_DIM + c);
    float4 o;
    o.x = w0 * a.x + w1 * b.x;
    o.y = w0 * a.y + w1 * b.y;
    o.z = w0 * a.z + w1 * b.z;
    o.w = w0 * a.w + w1 * b.w;
    *(float4*)(out + (size_t)t * H_DIM + c) = o;
}

// ---------------- launch ------------------------------------------------------
extern "C" void kernel_launch(void* const* d_in, const int* in_sizes, int n_in,
                              void* d_out, int out_size) {
    const float* x  = (const float*)d_in[0];  // [B,S,H]
    const float* w1 = (const float*)d_in[1];  // [E,H,F]
    const float* b1 = (const float*)d_in[2];  // [E,F]
    const float* w2 = (const float*)d_in[3];  // [E,F,H]
    const float* b2 = (const float*)d_in[4];  // [E,H]
    const float* rw = (const float*)d_in[5];  // [H,E]
    const float* rb = (const float*)d_in[6];  // [E]
    float* out = (float*)d_out;

    cudaFuncSetAttribute(moe_mma<false>, cudaFuncAttributeMaxDynamicSharedMemorySize,
                         SMEM_DYN);
    cudaFuncSetAttribute(moe_mma<true>, cudaFuncAttributeMaxDynamicSharedMemorySize,
                         SMEM_DYN);

    static __half *p_w1h = nullptr, *p_w2h = nullptr, *p_xh = nullptr;
    if (!p_w1h) {
        cudaGetSymbolAddress((void**)&p_w1h, g_w1h);
        cudaGetSymbolAddress((void**)&p_w2h, g_w2h);
        cudaGetSymbolAddress((void**)&p_xh, g_xh);
    }

    zero_counts_kernel<<<1, 32>>>();
    router_kernel<<<T_TOK / 8, 256>>>(x, rw, rb);
    scan_kernel<<<1, 32>>>();

    to_half_kernel<<<4096, 256>>>(w1, p_w1h, (size_t)NE * H_DIM * F_DIM / 8);
    to_half_kernel<<<4096, 256>>>(w2, p_w2h, (size_t)NE * F_DIM * H_DIM / 8);
    to_half_kernel<<<1024, 256>>>(x, p_xh, (size_t)T_TOK * H_DIM / 8);

    dim3 block(256);
    dim3 grid1(F_DIM / BN, T_TOK / BM, NE);  // 32 x 64 x 8
    dim3 grid2(H_DIM / BN, T_TOK / BM, NE);  //  8 x 64 x 8
    moe_mma<false><<<grid1, block, SMEM_DYN>>>(p_xh, p_w1h, b1);
    moe_mma<true ><<<grid2, block, SMEM_DYN>>>(nullptr, p_w2h, b2);
    combine_kernel<<<T_TOK, 256>>>(out);
}

// round 10
// speedup vs baseline: 13.0350x; 1.5021x over previous
#include <cuda_runtime.h>
#include <cuda_fp16.h>
#include <math.h>
#include <stdint.h>

#define T_TOK 8192
#define H_DIM 1024
#define F_DIM 4096
#define NE    8
#define BM    128
#define BN    128
#define BK    64
#define DEPTH 3

// ---------------- device scratch (static, no runtime allocation) ------------
__device__ __half g_h  [(size_t)(2 * T_TOK + BM) * F_DIM];  // gelu(x@w1+b1) fp16
__device__ float  g_h2 [(size_t)(2 * T_TOK + BM) * H_DIM];  // (h@w2+b2) fp32
__device__ __half g_w1h[(size_t)NE * H_DIM * F_DIM];        // fp16 w1
__device__ __half g_w2h[(size_t)NE * F_DIM * H_DIM];        // fp16 w2
__device__ __half g_xh [(size_t)T_TOK * H_DIM];             // fp16 x
__device__ int    g_tok[NE * T_TOK];
__device__ int    g_cnt[NE];
__device__ int    g_off[NE];
__device__ int    g_pE[2 * T_TOK];
__device__ int    g_pP[2 * T_TOK];
__device__ float  g_pW[2 * T_TOK];

// ---------------- helpers ----------------------------------------------------
__device__ __forceinline__ void mma16(float* d, const uint32_t* a, const uint32_t* b) {
    asm volatile(
        "mma.sync.aligned.m16n8k16.row.col.f32.f16.f16.f32 "
        "{%0,%1,%2,%3}, {%4,%5,%6,%7}, {%8,%9}, {%0,%1,%2,%3};"
        : "+f"(d[0]), "+f"(d[1]), "+f"(d[2]), "+f"(d[3])
        : "r"(a[0]), "r"(a[1]), "r"(a[2]), "r"(a[3]), "r"(b[0]), "r"(b[1]));
}
__device__ __forceinline__ void ldm4(uint32_t* r, uint32_t addr) {
    asm volatile("ldmatrix.sync.aligned.m8n8.x4.shared.b16 {%0,%1,%2,%3}, [%4];"
                 : "=r"(r[0]), "=r"(r[1]), "=r"(r[2]), "=r"(r[3]) : "r"(addr));
}
__device__ __forceinline__ void ldm4t(uint32_t* r, uint32_t addr) {
    asm volatile("ldmatrix.sync.aligned.m8n8.x4.trans.shared.b16 {%0,%1,%2,%3}, [%4];"
                 : "=r"(r[0]), "=r"(r[1]), "=r"(r[2]), "=r"(r[3]) : "r"(addr));
}
__device__ __forceinline__ uint32_t smem_u32(const void* p) {
    uint32_t a;
    asm("{ .reg .u64 t; cvta.to.shared.u64 t, %1; cvt.u32.u64 %0, t; }" : "=r"(a) : "l"(p));
    return a;
}
__device__ __forceinline__ void cp16(uint32_t dst, const void* src, bool pred) {
    int sz = pred ? 16 : 0;
    asm volatile("cp.async.cg.shared.global [%0], [%1], 16, %2;"
                 :: "r"(dst), "l"(src), "r"(sz) : "memory");
}
__device__ __forceinline__ void cp_commit() {
    asm volatile("cp.async.commit_group;" ::: "memory");
}
template <int N>
__device__ __forceinline__ void cp_wait() {
    asm volatile("cp.async.wait_group %0;" :: "n"(N) : "memory");
}
__device__ __forceinline__ float gelu_tanh(float v) {
    float u = 0.7978845608028654f * (v + 0.044715f * v * v * v);
    return 0.5f * v * (1.0f + tanhf(u));
}

// ---------------- fp32 -> fp16 convert pass ----------------------------------
__global__ __launch_bounds__(256) void to_half_kernel(const float* __restrict__ src,
                                                      __half* __restrict__ dst,
                                                      size_t n8) {
    size_t stride = (size_t)gridDim.x * blockDim.x;
    for (size_t i = blockIdx.x * (size_t)blockDim.x + threadIdx.x; i < n8; i += stride) {
        float4 v0 = ((const float4*)src)[2 * i];
        float4 v1 = ((const float4*)src)[2 * i + 1];
        __half2 h0 = __floats2half2_rn(v0.x, v0.y);
        __half2 h1 = __floats2half2_rn(v0.z, v0.w);
        __half2 h2 = __floats2half2_rn(v1.x, v1.y);
        __half2 h3 = __floats2half2_rn(v1.z, v1.w);
        uint4 o = {*(uint32_t*)&h0, *(uint32_t*)&h1, *(uint32_t*)&h2, *(uint32_t*)&h3};
        ((uint4*)dst)[i] = o;
    }
}

// ---------------- router ------------------------------------------------------
__global__ void zero_counts_kernel() {
    if (threadIdx.x < NE) g_cnt[threadIdx.x] = 0;
}
__global__ void scan_kernel() {
    if (threadIdx.x == 0) {
        int s = 0;
        for (int e = 0; e < NE; e++) { g_off[e] = s; s += g_cnt[e]; }
    }
}
__global__ __launch_bounds__(256) void router_kernel(const float* __restrict__ x,
                                                     const float* __restrict__ rw,
                                                     const float* __restrict__ rb) {
    int warp = threadIdx.x >> 5, lane = threadIdx.x & 31;
    int t = blockIdx.x * 8 + warp;
    if (t >= T_TOK) return;
    const float* xr = x + (size_t)t * H_DIM;
    float acc[NE];
#pragma unroll
    for (int e = 0; e < NE; e++) acc[e] = 0.f;
    for (int h = lane; h < H_DIM; h += 32) {
        float xv = xr[h];
        const float* wr = rw + h * NE;
#pragma unroll
        for (int e = 0; e < NE; e++) acc[e] += xv * wr[e];
    }
#pragma unroll
    for (int off = 16; off > 0; off >>= 1)
#pragma unroll
        for (int e = 0; e < NE; e++) acc[e] += __shfl_xor_sync(0xffffffffu, acc[e], off);
    if (lane == 0) {
#pragma unroll
        for (int e = 0; e < NE; e++) acc[e] += rb[e];
        int i1 = 0;
#pragma unroll
        for (int e = 1; e < NE; e++) if (acc[e] > acc[i1]) i1 = e;
        int i2 = -1;
#pragma unroll
        for (int e = 0; e < NE; e++) {
            if (e == i1) continue;
            if (i2 < 0 || acc[e] > acc[i2]) i2 = e;
        }
        float d   = acc[i2] - acc[i1];
        float w1p = 1.f / (1.f + expf(d));
        float w2p = 1.f - w1p;
        int p1 = atomicAdd(&g_cnt[i1], 1);
        g_tok[i1 * T_TOK + p1] = t;
        g_pE[2 * t] = i1; g_pP[2 * t] = p1; g_pW[2 * t] = w1p;
        int p2 = atomicAdd(&g_cnt[i2], 1);
        g_tok[i2 * T_TOK + p2] = t;
        g_pE[2 * t + 1] = i2; g_pP[2 * t + 1] = p2; g_pW[2 * t + 1] = w2p;
    }
}

// ---------------- fp16 mma.sync GEMM, BK=64, cp.async ring -------------------
// A smem: 128 rows x 64 half, row stride 144B -> ldmatrix conflict-free
// B smem: 64 k-rows x 128 half, row stride 272B -> ldm.trans conflict-free
#define A_STRIDE_B 144
#define B_STRIDE_B 272
#define A_BYTES   (BM * A_STRIDE_B)                 // 18432
#define B_BYTES   (BK * B_STRIDE_B)                 // 17408
#define STG_BYTES (A_BYTES + B_BYTES)               // 35840
#define SMEM_DYN  (DEPTH * STG_BYTES)               // 107520

template <bool PHASE2>
__global__ __launch_bounds__(256, 2) void moe_mma(const __half* __restrict__ X,
                                                  const __half* __restrict__ W,
                                                  const float* __restrict__ Bias) {
    constexpr int KDIM   = PHASE2 ? F_DIM : H_DIM;
    constexpr int NDIM   = PHASE2 ? H_DIM : F_DIM;
    constexpr int STAGES = KDIM / BK;               // 16 / 64

    const int e    = blockIdx.z;
    const int cnt  = g_cnt[e];
    const int row0 = blockIdx.y * BM;
    if (row0 >= cnt) return;
    const int col0 = blockIdx.x * BN;
    const int off  = g_off[e];
    const __half* Wexp = W + (size_t)e * KDIM * NDIM;

    extern __shared__ uint32_t smu[];
    __shared__ int toks_s[BM];
    const int tid = threadIdx.x;
    if (!PHASE2 && tid < BM) {
        int pos = row0 + tid;
        toks_s[tid] = (pos < cnt) ? g_tok[e * T_TOK + pos] : -1;
    }
    __syncthreads();

    // A loader: row = tid&127, half-of-row = tid>>7 -> 4x16B each (16KB/stage)
    const int arow = tid & 127, ah = tid >> 7;
    const __half* aptr;
    bool avalid = true;
    if (PHASE2) {
        aptr = g_h + (size_t)(off + row0 + arow) * F_DIM;
    } else {
        int tk = toks_s[arow];
        avalid = tk >= 0;
        aptr = avalid ? (X + (size_t)tk * H_DIM) : X;
    }
    // B loader: rows bk0+16i (i=0..3), chunk bc of 16 -> 4x16B each (16KB/stage)
    const int bk0 = tid >> 4, bc = tid & 15;
    const __half* bbase = Wexp + (size_t)bk0 * NDIM + col0 + bc * 8;

    const uint32_t smem_base = smem_u32(smu);
    const uint32_t a_off = (uint32_t)(arow * A_STRIDE_B + ah * 64);
    const uint32_t b_off = (uint32_t)(A_BYTES + bk0 * B_STRIDE_B + bc * 16);

    const int lane = tid & 31;
    const int g  = lane >> 2, t4 = lane & 3;
    const int wm = (tid >> 5) >> 2, wn = (tid >> 5) & 3;

    // A fragment base (ldmatrix x4): row = lane&15, +16B for k-high 8
    uint32_t a_frag_off[4];
#pragma unroll
    for (int mt = 0; mt < 4; mt++)
        a_frag_off[mt] = (uint32_t)((wm * 64 + mt * 16 + (lane & 15)) * A_STRIDE_B +
                                    (lane >> 4) * 16);
    // B fragment base (ldmatrix x4 trans): krow = (lane&7) + ((lane>>3)&1)*8
    uint32_t b_frag_off[2];
#pragma unroll
    for (int ntp = 0; ntp < 2; ntp++)
        b_frag_off[ntp] = (uint32_t)(A_BYTES +
            ((lane & 7) + ((lane >> 3) & 1) * 8) * B_STRIDE_B +
            wn * 64 + ntp * 32 + (lane >> 4) * 16);

    float acc[4][4][4];
#pragma unroll
    for (int mt = 0; mt < 4; mt++)
#pragma unroll
        for (int nt = 0; nt < 4; nt++)
#pragma unroll
            for (int r = 0; r < 4; r++) acc[mt][nt][r] = 0.f;

    auto issue = [&](int t) {
        uint32_t sb = smem_base + (uint32_t)(t % DEPTH) * STG_BYTES;
        int k0 = t * BK;
#pragma unroll
        for (int j = 0; j < 4; j++)
            cp16(sb + a_off + (uint32_t)(((ah * 4 + j) & 7) - ah * 4) * 0u +
                     (uint32_t)j * 16u,
                 aptr + k0 + ah * 32 + j * 8, avalid);
#pragma unroll
        for (int i = 0; i < 4; i++)
            cp16(sb + b_off + (uint32_t)(i * 16 * B_STRIDE_B),
                 bbase + (size_t)(k0 + i * 16) * NDIM, true);
        cp_commit();
    };

#pragma unroll
    for (int t = 0; t < DEPTH - 1; t++) issue(t);

    for (int s = 0; s < STAGES; s++) {
        cp_wait<DEPTH - 2>();
        __syncthreads();
        if (s + DEPTH - 1 < STAGES) issue(s + DEPTH - 1);

        const uint32_t sslot = smem_base + (uint32_t)(s % DEPTH) * STG_BYTES;
#pragma unroll
        for (int ks = 0; ks < 4; ks++) {          // four k16 steps per BK=64
            uint32_t af[4][4], bf[2][4];
#pragma unroll
            for (int mt = 0; mt < 4; mt++)
                ldm4(af[mt], sslot + a_frag_off[mt] + (uint32_t)ks * 32u);
#pragma unroll
            for (int ntp = 0; ntp < 2; ntp++)
                ldm4t(bf[ntp], sslot + b_frag_off[ntp] + (uint32_t)(ks * 16 * B_STRIDE_B));
#pragma unroll
            for (int mt = 0; mt < 4; mt++)
#pragma unroll
                for (int ntp = 0; ntp < 2; ntp++) {
                    mma16(acc[mt][2 * ntp],     af[mt], &bf[ntp][0]);
                    mma16(acc[mt][2 * ntp + 1], af[mt], &bf[ntp][2]);
                }
        }
    }

    // ---- epilogue: c0/c1 at row g, c2/c3 at row g+8, cols 2*t4 (+1)
#pragma unroll
    for (int mt = 0; mt < 4; mt++) {
#pragma unroll
        for (int rr = 0; rr < 2; rr++) {
            int m   = wm * 64 + mt * 16 + g + rr * 8;
            int pos = row0 + m;
            if (pos >= cnt) continue;
#pragma unroll
            for (int nt = 0; nt < 4; nt++) {
                int n = col0 + wn * 32 + nt * 8 + 2 * t4;
                float v0 = acc[mt][nt][rr * 2 + 0] + Bias[e * NDIM + n];
                float v1 = acc[mt][nt][rr * 2 + 1] + Bias[e * NDIM + n + 1];
                if (!PHASE2) {
                    __half2 o = __floats2half2_rn(gelu_tanh(v0), gelu_tanh(v1));
                    *(uint32_t*)(g_h + (size_t)(off + pos) * F_DIM + n) =
                        *(uint32_t*)&o;
                } else {
                    float2 o = {v0, v1};
                    *(float2*)(g_h2 + (size_t)(off + pos) * H_DIM + n) = o;
                }
            }
        }
    }
}

// ---------------- combine: out[t] = w0*h2[slot0] + w1*h2[slot1] --------------
__global__ __launch_bounds__(256) void combine_kernel(float* __restrict__ out) {
    int t = blockIdx.x;
    int c = threadIdx.x * 4;
    int e0 = g_pE[2 * t],     e1 = g_pE[2 * t + 1];
    int s0 = g_off[e0] + g_pP[2 * t];
    int s1 = g_off[e1] + g_pP[2 * t + 1];
    float w0 = g_pW[2 * t], w1 = g_pW[2 * t + 1];
    float4 a = *(const float4*)(g_h2 + (size_t)s0 * H_DIM + c);
    float4 b = *(const float4*)(g_h2 + (size_t)s1 * H_DIM + c);
    float4 o;
    o.x = w0 * a.x + w1 * b.x;
    o.y = w0 * a.y + w1 * b.y;
    o.z = w0 * a.z + w1 * b.z;
    o.w = w0 * a.w + w1 * b.w;
    *(float4*)(out + (size_t)t * H_DIM + c) = o;
}

// ---------------- launch ------------------------------------------------------
extern "C" void kernel_launch(void* const* d_in, const int* in_sizes, int n_in,
                              void* d_out, int out_size) {
    const float* x  = (const float*)d_in[0];  // [B,S,H]
    const float* w1 = (const float*)d_in[1];  // [E,H,F]
    const float* b1 = (const float*)d_in[2];  // [E,F]
    const float* w2 = (const float*)d_in[3];  // [E,F,H]
    const float* b2 = (const float*)d_in[4];  // [E,H]
    const float* rw = (const float*)d_in[5];  // [H,E]
    const float* rb = (const float*)d_in[6];  // [E]
    float* out = (float*)d_out;

    cudaFuncSetAttribute(moe_mma<false>, cudaFuncAttributeMaxDynamicSharedMemorySize,
                         SMEM_DYN);
    cudaFuncSetAttribute(moe_mma<true>, cudaFuncAttributeMaxDynamicSharedMemorySize,
                         SMEM_DYN);

    static __half *p_w1h = nullptr, *p_w2h = nullptr, *p_xh = nullptr;
    if (!p_w1h) {
        cudaGetSymbolAddress((void**)&p_w1h, g_w1h);
        cudaGetSymbolAddress((void**)&p_w2h, g_w2h);
        cudaGetSymbolAddress((void**)&p_xh, g_xh);
    }

    dim3 block(256);
    dim3 grid1(F_DIM / BN, T_TOK / BM, NE);  // 32 x 64 x 8
    dim3 grid2(H_DIM / BN, T_TOK / BM, NE);  //  8 x 64 x 8

    // order chosen so ncu -s 5 samples moe_mma<false>
    to_half_kernel<<<1024, 256>>>(x, p_xh, (size_t)T_TOK * H_DIM / 8);      // 0
    zero_counts_kernel<<<1, 32>>>();                                        // 1
    router_kernel<<<T_TOK / 8, 256>>>(x, rw, rb);                           // 2
    scan_kernel<<<1, 32>>>();                                               // 3
    to_half_kernel<<<4096, 256>>>(w1, p_w1h, (size_t)NE * H_DIM * F_DIM / 8); // 4
    moe_mma<false><<<grid1, block, SMEM_DYN>>>(p_xh, p_w1h, b1);            // 5
    to_half_kernel<<<4096, 256>>>(w2, p_w2h, (size_t)NE * F_DIM * H_DIM / 8); // 6
    moe_mma<true ><<<grid2, block, SMEM_DYN>>>(nullptr, p_w2h, b2);         // 7
    combine_kernel<<<T_TOK, 256>>>(out);                                    // 8
}